// round 5
// baseline (speedup 1.0000x reference)
#include <cuda_runtime.h>

#define CCH   256
#define FH    50
#define FW    50
#define HW    (FH*FW)
#define OUTS  7
#define SPAN  3           // bilinear footprint per ROI axis (roi extent < 1 px)
#define EX    8           // extracted corner size (max index used is 5)
#define NPIX  (EX*EX)     // 64

// Extracted, channel-contiguous corner of the feature map: [64 pixels][256 ch].
__device__ float g_fmt[NPIX * CCH];

// ---------------------------------------------------------------------------
// Corner extraction as a tiled transpose over the 8x8 used corner.
// grid (2, 8), block (32, 32): pix tiles x channel tiles. Reads hit 4
// consecutive-8-float runs per warp; writes fully coalesced.
// ---------------------------------------------------------------------------
__global__ void extract_kernel(const float* __restrict__ fm) {
    __shared__ float tile[32][33];
    int pix = blockIdx.x * 32 + threadIdx.x;        // 0..63
    int c   = blockIdx.y * 32 + threadIdx.y;
    int fmo = (pix >> 3) * FW + (pix & 7);          // 8x8 corner -> fm offset
    tile[threadIdx.y][threadIdx.x] = fm[c * HW + fmo];
    __syncthreads();
    int c2   = blockIdx.y * 32 + threadIdx.x;
    int pix2 = blockIdx.x * 32 + threadIdx.y;
    g_fmt[pix2 * CCH + c2] = tile[threadIdx.x][threadIdx.y];
}

// ---------------------------------------------------------------------------
// ROI-align kernel: grid N*2 (128-channel halves), 128 threads, 4 autonomous
// warps. No __syncthreads anywhere — per-warp setup, staging, and copy-out.
// out[oy][ox] = sum_r RW[oy][r] * sum_c CW[ox][c] * patch[r][c]
// (RW includes the 1/(sr*sr)=0.25 mean factor.)
// ---------------------------------------------------------------------------
__global__ __launch_bounds__(128, 8) void roi_kernel(
    const float* __restrict__ props, float* __restrict__ out)
{
    __shared__ __align__(16) float obuf[128 * OUTS * OUTS];  // 25088 B staging
    __shared__ float wts[4][2][OUTS][SPAN];   // per-warp [axis][o][r]
    __shared__ int   sbase[4][2];             // per-warp rowbase/colbase

    const int n    = blockIdx.x >> 1;
    const int half = blockIdx.x & 1;
    const int tid  = threadIdx.x;
    const int wid  = tid >> 5;
    const int lane = tid & 31;

    // ---- per-warp weight setup: lanes 0..13, one per (axis, o) ----
    if (lane < 2 * OUTS) {
        const int axis = lane >= OUTS;       // 0 = y, 1 = x
        const int o    = (axis ? lane - OUTS : lane);
        const float sc = 1.0f / 256.0f;      // SCALE applied twice in ref (exact)
        float a1 = __fmul_rn(props[n * 4 + (axis == 0 ? 1 : 0)], sc);
        float a2 = __fmul_rn(props[n * 4 + (axis == 0 ? 3 : 2)], sc);
        float roi   = fmaxf(__fadd_rn(a2, -a1), 1.0f);
        float binsz = __fdiv_rn(roi, 7.0f);
        const float Lf = 50.0f;
        const int   Li = 49;

        // base = i0 of sample 0 (i0 monotone in s).
        int base;
        {
            float v  = __fadd_rn(a1, __fmul_rn(binsz, 0.25f));
            float vc = fminf(fmaxf(v, 0.0f), Lf - 1.0f);
            base = min((int)floorf(vc), Li);
        }
        if (o == 0) sbase[wid][axis] = base;

        float w0 = 0.0f, w1 = 0.0f, w2 = 0.0f;
        #pragma unroll
        for (int k = 0; k < 2; k++) {
            int s = 2 * o + k;
            float g = ((float)s + 0.5f) * 0.5f;
            float v = __fadd_rn(a1, __fmul_rn(binsz, g));
            bool valid = (v >= -1.0f) && (v <= Lf);
            float vc = fminf(fmaxf(v, 0.0f), Lf - 1.0f);
            int i0 = min((int)floorf(vc), Li);
            int i1 = min(i0 + 1, Li);
            float l = vc - (float)i0;
            float h = 1.0f - l;
            if (!valid) { h = 0.0f; l = 0.0f; }
            int r0 = min(i0 - base, SPAN - 1);
            int r1 = min(i1 - base, SPAN - 1);
            if (r0 == 0) w0 += h; else if (r0 == 1) w1 += h; else w2 += h;
            if (r1 == 0) w0 += l; else if (r1 == 1) w1 += l; else w2 += l;
        }
        float f = (axis == 0) ? 0.25f : 1.0f;   // fold sr*sr mean into y weights
        wts[wid][axis][o][0] = w0 * f;
        wts[wid][axis][o][1] = w1 * f;
        wts[wid][axis][o][2] = w2 * f;
    }
    __syncwarp();

    // ---- issue patch loads ASAP (only rb/cb needed) ----
    const int ch = half * 128 + tid;
    const int rb = sbase[wid][0];
    const int cb = sbase[wid][1];

    // rb,cb <= 3 and rb+2,cb+2 <= 5 < 8: no clamps needed.
    float patch[SPAN][SPAN];
    #pragma unroll
    for (int r = 0; r < SPAN; r++)
        #pragma unroll
        for (int c = 0; c < SPAN; c++)
            patch[r][c] = g_fmt[(((rb + r) << 3) + cb + c) * CCH + ch];

    // x pass: tmp[r][ox] = sum_c patch[r][c] * CW[ox][c]
    float tmp[SPAN][OUTS];
    #pragma unroll
    for (int r = 0; r < SPAN; r++)
        #pragma unroll
        for (int ox = 0; ox < OUTS; ox++) {
            float s = patch[r][0] * wts[wid][1][ox][0];
            s = fmaf(patch[r][1], wts[wid][1][ox][1], s);
            s = fmaf(patch[r][2], wts[wid][1][ox][2], s);
            tmp[r][ox] = s;
        }

    // y pass, staged into this warp's obuf slice.
    float* ob = obuf + tid * (OUTS * OUTS);
    #pragma unroll
    for (int oy = 0; oy < OUTS; oy++)
        #pragma unroll
        for (int ox = 0; ox < OUTS; ox++) {
            float s = wts[wid][0][oy][0] * tmp[0][ox];
            s = fmaf(wts[wid][0][oy][1], tmp[1][ox], s);
            s = fmaf(wts[wid][0][oy][2], tmp[2][ox], s);
            ob[oy * OUTS + ox] = s;
        }
    __syncwarp();

    // ---- per-warp coalesced float4 copy-out: 32 channels = 1568 floats ----
    const int WF4 = 32 * OUTS * OUTS / 4;     // 392 float4 per warp
    const float4* src = (const float4*)(obuf + wid * 32 * OUTS * OUTS);
    float4* dst = (float4*)(out +
        ((size_t)n * CCH + (size_t)half * 128 + (size_t)wid * 32) * (OUTS * OUTS));
    #pragma unroll 4
    for (int i = lane; i < WF4; i += 32)
        dst[i] = src[i];
}

extern "C" void kernel_launch(void* const* d_in, const int* in_sizes, int n_in,
                              void* d_out, int out_size) {
    const float* fm    = (const float*)d_in[0];
    const float* props = (const float*)d_in[1];
    float* out = (float*)d_out;
    int N = in_sizes[1] / 4;

    dim3 tb(32, 32);
    dim3 tg(2, 8);                 // 64 pixels x 256 channels
    extract_kernel<<<tg, tb>>>(fm);
    roi_kernel<<<N * 2, 128>>>(props, out);
}

// round 6
// speedup vs baseline: 1.0643x; 1.0643x over previous
#include <cuda_runtime.h>
#include <cstdint>

#define CCH   256
#define FH    50
#define FW    50
#define HW    (FH*FW)
#define OUTS  7
#define SPAN  3           // bilinear footprint per ROI axis (roi extent < 1 px)
#define EX    8           // extracted corner size (max index used is 5)
#define NPIX  (EX*EX)     // 64
#define OBUF_FLOATS (128 * OUTS * OUTS)   // 6272 floats = 25088 B per block

// Extracted, channel-contiguous corner of the feature map: [64 pixels][256 ch].
__device__ float g_fmt[NPIX * CCH];

// ---------------------------------------------------------------------------
// Corner extraction as a tiled transpose over the 8x8 used corner.
// ---------------------------------------------------------------------------
__global__ void extract_kernel(const float* __restrict__ fm) {
    __shared__ float tile[32][33];
    int pix = blockIdx.x * 32 + threadIdx.x;        // 0..63
    int c   = blockIdx.y * 32 + threadIdx.y;
    int fmo = (pix >> 3) * FW + (pix & 7);          // 8x8 corner -> fm offset
    tile[threadIdx.y][threadIdx.x] = fm[c * HW + fmo];
    __syncthreads();
    int c2   = blockIdx.y * 32 + threadIdx.x;
    int pix2 = blockIdx.x * 32 + threadIdx.y;
    g_fmt[pix2 * CCH + c2] = tile[threadIdx.x][threadIdx.y];
}

// ---------------------------------------------------------------------------
// ROI-align kernel: grid N*2 (128-channel halves), 128 threads.
// Compute identical to R5 (validated, rel_err 6e-8). The change: the staged
// output block (25088 B, contiguous in gmem) leaves via ONE TMA bulk store
// instead of per-thread LDS.128+STG.128 — removing ~2/3 of per-warp LSU work
// and moving the copy onto the async engine at the LTS cap.
// ---------------------------------------------------------------------------
__global__ __launch_bounds__(128, 8) void roi_kernel(
    const float* __restrict__ props, float* __restrict__ out)
{
    __shared__ __align__(16) float obuf[OBUF_FLOATS];  // 25088 B staging
    __shared__ float wts[4][2][OUTS][SPAN];   // per-warp [axis][o][r]
    __shared__ int   sbase[4][2];             // per-warp rowbase/colbase

    const int n    = blockIdx.x >> 1;
    const int tid  = threadIdx.x;
    const int wid  = tid >> 5;
    const int lane = tid & 31;

    // ---- per-warp weight setup: lanes 0..13, one per (axis, o) ----
    if (lane < 2 * OUTS) {
        const int axis = lane >= OUTS;       // 0 = y, 1 = x
        const int o    = (axis ? lane - OUTS : lane);
        const float sc = 1.0f / 256.0f;      // SCALE applied twice in ref (exact)
        float a1 = __fmul_rn(props[n * 4 + (axis == 0 ? 1 : 0)], sc);
        float a2 = __fmul_rn(props[n * 4 + (axis == 0 ? 3 : 2)], sc);
        float roi   = fmaxf(__fadd_rn(a2, -a1), 1.0f);
        float binsz = __fdiv_rn(roi, 7.0f);
        const float Lf = 50.0f;
        const int   Li = 49;

        // base = i0 of sample 0 (i0 monotone in s).
        int base;
        {
            float v  = __fadd_rn(a1, __fmul_rn(binsz, 0.25f));
            float vc = fminf(fmaxf(v, 0.0f), Lf - 1.0f);
            base = min((int)floorf(vc), Li);
        }
        if (o == 0) sbase[wid][axis] = base;

        float w0 = 0.0f, w1 = 0.0f, w2 = 0.0f;
        #pragma unroll
        for (int k = 0; k < 2; k++) {
            int s = 2 * o + k;
            float g = ((float)s + 0.5f) * 0.5f;
            float v = __fadd_rn(a1, __fmul_rn(binsz, g));
            bool valid = (v >= -1.0f) && (v <= Lf);
            float vc = fminf(fmaxf(v, 0.0f), Lf - 1.0f);
            int i0 = min((int)floorf(vc), Li);
            int i1 = min(i0 + 1, Li);
            float l = vc - (float)i0;
            float h = 1.0f - l;
            if (!valid) { h = 0.0f; l = 0.0f; }
            int r0 = min(i0 - base, SPAN - 1);
            int r1 = min(i1 - base, SPAN - 1);
            if (r0 == 0) w0 += h; else if (r0 == 1) w1 += h; else w2 += h;
            if (r1 == 0) w0 += l; else if (r1 == 1) w1 += l; else w2 += l;
        }
        float f = (axis == 0) ? 0.25f : 1.0f;   // fold sr*sr mean into y weights
        wts[wid][axis][o][0] = w0 * f;
        wts[wid][axis][o][1] = w1 * f;
        wts[wid][axis][o][2] = w2 * f;
    }
    __syncwarp();

    // ---- per-channel compute ----
    const int ch = (blockIdx.x & 1) * 128 + tid;
    const int rb = sbase[wid][0];
    const int cb = sbase[wid][1];

    // rb,cb <= 3 and rb+2,cb+2 <= 5 < 8: no clamps needed.
    float patch[SPAN][SPAN];
    #pragma unroll
    for (int r = 0; r < SPAN; r++)
        #pragma unroll
        for (int c = 0; c < SPAN; c++)
            patch[r][c] = g_fmt[(((rb + r) << 3) + cb + c) * CCH + ch];

    // x pass: tmp[r][ox] = sum_c patch[r][c] * CW[ox][c]
    float tmp[SPAN][OUTS];
    #pragma unroll
    for (int r = 0; r < SPAN; r++)
        #pragma unroll
        for (int ox = 0; ox < OUTS; ox++) {
            float s = patch[r][0] * wts[wid][1][ox][0];
            s = fmaf(patch[r][1], wts[wid][1][ox][1], s);
            s = fmaf(patch[r][2], wts[wid][1][ox][2], s);
            tmp[r][ox] = s;
        }

    // y pass, staged into smem.
    float* ob = obuf + tid * (OUTS * OUTS);
    #pragma unroll
    for (int oy = 0; oy < OUTS; oy++)
        #pragma unroll
        for (int ox = 0; ox < OUTS; ox++) {
            float s = wts[wid][0][oy][0] * tmp[0][ox];
            s = fmaf(wts[wid][0][oy][1], tmp[1][ox], s);
            s = fmaf(wts[wid][0][oy][2], tmp[2][ox], s);
            ob[oy * OUTS + ox] = s;
        }
    __syncthreads();

    // ---- single TMA bulk store: 25088 B smem -> contiguous gmem ----
    if (tid == 0) {
        // Make the generic-proxy smem writes visible to the async proxy.
        asm volatile("fence.proxy.async.shared::cta;" ::: "memory");
        uint32_t s32;
        asm("{ .reg .u64 t; cvta.to.shared.u64 t, %1; cvt.u32.u64 %0, t; }"
            : "=r"(s32) : "l"(obuf));
        const float* dst = out + (size_t)blockIdx.x * OBUF_FLOATS;
        asm volatile(
            "cp.async.bulk.global.shared::cta.bulk_group [%0], [%1], %2;"
            :: "l"(dst), "r"(s32), "n"(OBUF_FLOATS * 4) : "memory");
        asm volatile("cp.async.bulk.commit_group;" ::: "memory");
        asm volatile("cp.async.bulk.wait_group 0;" ::: "memory");
    }
}

extern "C" void kernel_launch(void* const* d_in, const int* in_sizes, int n_in,
                              void* d_out, int out_size) {
    const float* fm    = (const float*)d_in[0];
    const float* props = (const float*)d_in[1];
    float* out = (float*)d_out;
    int N = in_sizes[1] / 4;

    dim3 tb(32, 32);
    dim3 tg(2, 8);                 // 64 pixels x 256 channels
    extract_kernel<<<tg, tb>>>(fm);
    roi_kernel<<<N * 2, 128>>>(props, out);
}

// round 7
// speedup vs baseline: 1.0869x; 1.0212x over previous
#include <cuda_runtime.h>
#include <cstdint>

#define CCH   256
#define FH    50
#define FW    50
#define HW    (FH*FW)
#define OUTS  7
#define SPAN  3           // bilinear footprint per ROI axis (roi extent < 1 px)
#define EX    8           // extracted corner size (max index used is 5)
#define NPIX  (EX*EX)     // 64
#define OBUF_FLOATS (128 * OUTS * OUTS)   // 6272 floats = 25088 B per block

// Extracted, channel-contiguous corner of the feature map: [64 pixels][256 ch].
__device__ float g_fmt[NPIX * CCH];

// ---------------------------------------------------------------------------
// Corner extraction as a tiled transpose over the 8x8 used corner.
// ---------------------------------------------------------------------------
__global__ void extract_kernel(const float* __restrict__ fm) {
    __shared__ float tile[32][33];
    int pix = blockIdx.x * 32 + threadIdx.x;        // 0..63
    int c   = blockIdx.y * 32 + threadIdx.y;
    int fmo = (pix >> 3) * FW + (pix & 7);          // 8x8 corner -> fm offset
    tile[threadIdx.y][threadIdx.x] = fm[c * HW + fmo];
    __syncthreads();
    int c2   = blockIdx.y * 32 + threadIdx.x;
    int pix2 = blockIdx.x * 32 + threadIdx.y;
    g_fmt[pix2 * CCH + c2] = tile[threadIdx.x][threadIdx.y];
}

// ---------------------------------------------------------------------------
// ROI-align kernel: grid N*2 (128-channel halves), 128 threads.
// Compute identical to R5 (validated, rel_err 6e-8). The change: the staged
// output block (25088 B, contiguous in gmem) leaves via ONE TMA bulk store
// instead of per-thread LDS.128+STG.128 — removing ~2/3 of per-warp LSU work
// and moving the copy onto the async engine at the LTS cap.
// ---------------------------------------------------------------------------
__global__ __launch_bounds__(128, 8) void roi_kernel(
    const float* __restrict__ props, float* __restrict__ out)
{
    __shared__ __align__(16) float obuf[OBUF_FLOATS];  // 25088 B staging
    __shared__ float wts[4][2][OUTS][SPAN];   // per-warp [axis][o][r]
    __shared__ int   sbase[4][2];             // per-warp rowbase/colbase

    const int n    = blockIdx.x >> 1;
    const int tid  = threadIdx.x;
    const int wid  = tid >> 5;
    const int lane = tid & 31;

    // ---- per-warp weight setup: lanes 0..13, one per (axis, o) ----
    if (lane < 2 * OUTS) {
        const int axis = lane >= OUTS;       // 0 = y, 1 = x
        const int o    = (axis ? lane - OUTS : lane);
        const float sc = 1.0f / 256.0f;      // SCALE applied twice in ref (exact)
        float a1 = __fmul_rn(props[n * 4 + (axis == 0 ? 1 : 0)], sc);
        float a2 = __fmul_rn(props[n * 4 + (axis == 0 ? 3 : 2)], sc);
        float roi   = fmaxf(__fadd_rn(a2, -a1), 1.0f);
        float binsz = __fdiv_rn(roi, 7.0f);
        const float Lf = 50.0f;
        const int   Li = 49;

        // base = i0 of sample 0 (i0 monotone in s).
        int base;
        {
            float v  = __fadd_rn(a1, __fmul_rn(binsz, 0.25f));
            float vc = fminf(fmaxf(v, 0.0f), Lf - 1.0f);
            base = min((int)floorf(vc), Li);
        }
        if (o == 0) sbase[wid][axis] = base;

        float w0 = 0.0f, w1 = 0.0f, w2 = 0.0f;
        #pragma unroll
        for (int k = 0; k < 2; k++) {
            int s = 2 * o + k;
            float g = ((float)s + 0.5f) * 0.5f;
            float v = __fadd_rn(a1, __fmul_rn(binsz, g));
            bool valid = (v >= -1.0f) && (v <= Lf);
            float vc = fminf(fmaxf(v, 0.0f), Lf - 1.0f);
            int i0 = min((int)floorf(vc), Li);
            int i1 = min(i0 + 1, Li);
            float l = vc - (float)i0;
            float h = 1.0f - l;
            if (!valid) { h = 0.0f; l = 0.0f; }
            int r0 = min(i0 - base, SPAN - 1);
            int r1 = min(i1 - base, SPAN - 1);
            if (r0 == 0) w0 += h; else if (r0 == 1) w1 += h; else w2 += h;
            if (r1 == 0) w0 += l; else if (r1 == 1) w1 += l; else w2 += l;
        }
        float f = (axis == 0) ? 0.25f : 1.0f;   // fold sr*sr mean into y weights
        wts[wid][axis][o][0] = w0 * f;
        wts[wid][axis][o][1] = w1 * f;
        wts[wid][axis][o][2] = w2 * f;
    }
    __syncwarp();

    // ---- per-channel compute ----
    const int ch = (blockIdx.x & 1) * 128 + tid;
    const int rb = sbase[wid][0];
    const int cb = sbase[wid][1];

    // rb,cb <= 3 and rb+2,cb+2 <= 5 < 8: no clamps needed.
    float patch[SPAN][SPAN];
    #pragma unroll
    for (int r = 0; r < SPAN; r++)
        #pragma unroll
        for (int c = 0; c < SPAN; c++)
            patch[r][c] = g_fmt[(((rb + r) << 3) + cb + c) * CCH + ch];

    // x pass: tmp[r][ox] = sum_c patch[r][c] * CW[ox][c]
    float tmp[SPAN][OUTS];
    #pragma unroll
    for (int r = 0; r < SPAN; r++)
        #pragma unroll
        for (int ox = 0; ox < OUTS; ox++) {
            float s = patch[r][0] * wts[wid][1][ox][0];
            s = fmaf(patch[r][1], wts[wid][1][ox][1], s);
            s = fmaf(patch[r][2], wts[wid][1][ox][2], s);
            tmp[r][ox] = s;
        }

    // y pass, staged into smem.
    float* ob = obuf + tid * (OUTS * OUTS);
    #pragma unroll
    for (int oy = 0; oy < OUTS; oy++)
        #pragma unroll
        for (int ox = 0; ox < OUTS; ox++) {
            float s = wts[wid][0][oy][0] * tmp[0][ox];
            s = fmaf(wts[wid][0][oy][1], tmp[1][ox], s);
            s = fmaf(wts[wid][0][oy][2], tmp[2][ox], s);
            ob[oy * OUTS + ox] = s;
        }
    __syncthreads();

    // ---- single TMA bulk store: 25088 B smem -> contiguous gmem ----
    if (tid == 0) {
        // Make the generic-proxy smem writes visible to the async proxy.
        asm volatile("fence.proxy.async.shared::cta;" ::: "memory");
        uint32_t s32;
        asm("{ .reg .u64 t; cvta.to.shared.u64 t, %1; cvt.u32.u64 %0, t; }"
            : "=r"(s32) : "l"(obuf));
        const float* dst = out + (size_t)blockIdx.x * OBUF_FLOATS;
        asm volatile(
            "cp.async.bulk.global.shared::cta.bulk_group [%0], [%1], %2;"
            :: "l"(dst), "r"(s32), "n"(OBUF_FLOATS * 4) : "memory");
        asm volatile("cp.async.bulk.commit_group;" ::: "memory");
        asm volatile("cp.async.bulk.wait_group 0;" ::: "memory");
    }
}

extern "C" void kernel_launch(void* const* d_in, const int* in_sizes, int n_in,
                              void* d_out, int out_size) {
    const float* fm    = (const float*)d_in[0];
    const float* props = (const float*)d_in[1];
    float* out = (float*)d_out;
    int N = in_sizes[1] / 4;

    dim3 tb(32, 32);
    dim3 tg(2, 8);                 // 64 pixels x 256 channels
    extract_kernel<<<tg, tb>>>(fm);
    roi_kernel<<<N * 2, 128>>>(props, out);
}